// round 9
// baseline (speedup 1.0000x reference)
#include <cuda_runtime.h>
#include <cuda_bf16.h>
#include <cstdint>

#define SEQ   2048
#define EMB   1024
#define NH    16
#define HSZ   64
#define BATCH 2
#define ROWS  (BATCH * SEQ)     // 4096
#define D3    (3 * EMB)         // 3072
#define NCK   (EMB / 32)        // 32 k-stages of BK=32 for projection GEMMs

// Scratch (device globals — no allocation allowed)
__device__ __nv_bfloat16 g_qkvh[ROWS * D3];  // qkv hi  [b*s][3*EMB]
__device__ __nv_bfloat16 g_qkvl[ROWS * D3];  // qkv lo
__device__ __nv_bfloat16 g_wt1h[D3 * EMB];   // W_qkv^T hi  [3072,1024] (K-major)
__device__ __nv_bfloat16 g_wt1l[D3 * EMB];
__device__ __nv_bfloat16 g_wt2h[EMB * EMB];  // W_out^T hi
__device__ __nv_bfloat16 g_wt2l[EMB * EMB];
__device__ __nv_bfloat16 g_xh[ROWS * EMB];   // x hi/lo
__device__ __nv_bfloat16 g_xl[ROWS * EMB];
__device__ __nv_bfloat16 g_oh[ROWS * EMB];   // attn-out hi/lo
__device__ __nv_bfloat16 g_ol[ROWS * EMB];

// ============================================================================
// asm helpers (plain sm_80+ PTX — legal on target sm_103)
// ============================================================================
__device__ __forceinline__ uint32_t smem_to_u32(const void* p) {
    uint32_t a;
    asm("{ .reg .u64 t; cvta.to.shared.u64 t, %1; cvt.u32.u64 %0, t; }"
        : "=r"(a) : "l"(p));
    return a;
}

#define CP_ASYNC16(dst, src) \
    asm volatile("cp.async.cg.shared.global [%0], [%1], 16;" \
                 :: "r"(dst), "l"(__cvta_generic_to_global(src)) : "memory")
#define CP_COMMIT() asm volatile("cp.async.commit_group;" ::: "memory")
#define CP_WAIT0()  asm volatile("cp.async.wait_group 0;" ::: "memory")
#define CP_WAIT1()  asm volatile("cp.async.wait_group 1;" ::: "memory")
#define CP_WAIT2()  asm volatile("cp.async.wait_group 2;" ::: "memory")

#define LDSM_X4(r0, r1, r2, r3, addr) \
    asm volatile("ldmatrix.sync.aligned.m8n8.x4.shared.b16 {%0,%1,%2,%3}, [%4];" \
                 : "=r"(r0), "=r"(r1), "=r"(r2), "=r"(r3) : "r"(addr))
#define LDSM_X4T(r0, r1, r2, r3, addr) \
    asm volatile("ldmatrix.sync.aligned.m8n8.x4.trans.shared.b16 {%0,%1,%2,%3}, [%4];" \
                 : "=r"(r0), "=r"(r1), "=r"(r2), "=r"(r3) : "r"(addr))

#define MMA_BF16(d, a, b0v, b1v) \
    asm volatile("mma.sync.aligned.m16n8k16.row.col.f32.bf16.bf16.f32 " \
                 "{%0,%1,%2,%3}, {%4,%5,%6,%7}, {%8,%9}, {%0,%1,%2,%3};" \
                 : "+f"((d)[0]), "+f"((d)[1]), "+f"((d)[2]), "+f"((d)[3]) \
                 : "r"((a)[0]), "r"((a)[1]), "r"((a)[2]), "r"((a)[3]), \
                   "r"(b0v), "r"(b1v))

// pack two f32 -> bf16x2 (first arg in low half)
__device__ __forceinline__ uint32_t pack_bf16x2(float lo, float hi) {
    uint32_t r;
    asm("cvt.rn.bf16x2.f32 %0, %1, %2;" : "=r"(r) : "f"(hi), "f"(lo));
    return r;
}

// ============================================================================
// Prep: Wt[n][k] = W[k][n], split into bf16 hi/lo. W is [K, N] row-major.
// ============================================================================
template <int MODE>
__global__ void prep_wt(const float* __restrict__ W, int K, int N)
{
    __nv_bfloat16* Wh = (MODE == 0) ? g_wt1h : g_wt2h;
    __nv_bfloat16* Wl = (MODE == 0) ? g_wt1l : g_wt2l;
    __shared__ float t[32][33];
    const int n0 = blockIdx.x * 32, k0 = blockIdx.y * 32;
    const int tx = threadIdx.x, ty = threadIdx.y;
#pragma unroll
    for (int j = 0; j < 32; j += 8)
        t[ty + j][tx] = W[(long)(k0 + ty + j) * N + n0 + tx];
    __syncthreads();
#pragma unroll
    for (int j = 0; j < 32; j += 8) {
        const int n = n0 + ty + j, k = k0 + tx;
        float v = t[tx][ty + j];
        __nv_bfloat16 h = __float2bfloat16(v);
        Wh[(long)n * K + k] = h;
        Wl[(long)n * K + k] = __float2bfloat16(v - __bfloat162float(h));
    }
}

// x -> g_xh/g_xl (elementwise hi/lo split)
__global__ void prep_split_x(const float* __restrict__ s)
{
    const int i = blockIdx.x * blockDim.x + threadIdx.x;   // float4 index
    float4 v = ((const float4*)s)[i];
    union { __nv_bfloat16 b[4]; uint2 u; } ph, pl;
    ph.b[0] = __float2bfloat16(v.x);
    ph.b[1] = __float2bfloat16(v.y);
    ph.b[2] = __float2bfloat16(v.z);
    ph.b[3] = __float2bfloat16(v.w);
    pl.b[0] = __float2bfloat16(v.x - __bfloat162float(ph.b[0]));
    pl.b[1] = __float2bfloat16(v.y - __bfloat162float(ph.b[1]));
    pl.b[2] = __float2bfloat16(v.z - __bfloat162float(ph.b[2]));
    pl.b[3] = __float2bfloat16(v.w - __bfloat162float(ph.b[3]));
    ((uint2*)g_xh)[i] = ph.u;
    ((uint2*)g_xl)[i] = pl.u;
}

// ============================================================================
// HMMA GEMM + bias. 3-MMA split, dependency-spaced MMA issue order.
// CTA 128x128, BK=32, 8 warps (4m x 2n). Single __syncthreads per k-stage.
// MODE 0: A=g_xh/l, B=g_wt1*, writes g_qkvh/g_qkvl
// MODE 1: A=g_oh/l, B=g_wt2*, writes fp32 Cout (+bias)
// ============================================================================
#define GEMM_SMEM 81920

template <int MODE>
__global__ __launch_bounds__(256, 2)
void gemm_tc(const float* __restrict__ bias, float* __restrict__ Cout)
{
    const __nv_bfloat16* Ah = (MODE == 0) ? g_xh : g_oh;
    const __nv_bfloat16* Al = (MODE == 0) ? g_xl : g_ol;
    const __nv_bfloat16* Bh = (MODE == 0) ? g_wt1h : g_wt2h;
    const __nv_bfloat16* Bl = (MODE == 0) ? g_wt1l : g_wt2l;
    const int N = (MODE == 0) ? D3 : EMB;
    const int K = EMB;

    extern __shared__ char smem[];
    const uint32_t sb = smem_to_u32(smem);
    const int tid = threadIdx.x;
    const int wid = tid >> 5, lane = tid & 31;
    const int wm = wid & 3, wn = wid >> 2;
    const int m0 = blockIdx.y * 128, n0 = blockIdx.x * 128;

    const __nv_bfloat16* csrc[8];
    uint32_t cdst[8];
#pragma unroll
    for (int i = 0; i < 8; i++) {
        int g = i * 256 + tid;
        int sub = g >> 9, c = g & 511, row = c >> 2, ch = c & 3;
        const __nv_bfloat16* bp =
            (sub == 0) ? Ah + (long)m0 * K :
            (sub == 1) ? Al + (long)m0 * K :
            (sub == 2) ? Bh + (long)n0 * K :
                         Bl + (long)n0 * K;
        csrc[i] = bp + (long)row * K + ch * 8;
        cdst[i] = sb + sub * 10240 + row * 80 + ch * 16;
    }

#pragma unroll
    for (int i = 0; i < 8; i++) { CP_ASYNC16(cdst[i], csrc[i]); csrc[i] += 32; }
    CP_COMMIT();

    const uint32_t a_base = sb + (wm * 32 + (lane & 15)) * 80 + (lane >> 4) * 16;
    const uint32_t b_base = sb + 20480 +
        (wn * 64 + (lane & 7) + ((lane >> 4) & 1) * 8) * 80 + ((lane >> 3) & 1) * 16;

    float acc[2][8][4];
#pragma unroll
    for (int mf = 0; mf < 2; mf++)
#pragma unroll
        for (int nf = 0; nf < 8; nf++)
#pragma unroll
            for (int q = 0; q < 4; q++) acc[mf][nf][q] = 0.f;

    for (int ck = 0; ck < NCK; ck++) {
        const int buf = ck & 1;
        CP_WAIT0();            // stage ck landed
        __syncthreads();       // visible to all; prev compute (reads buf^1) done
        if (ck + 1 < NCK) {
            const uint32_t bo = (buf ^ 1) * 40960;
#pragma unroll
            for (int i = 0; i < 8; i++) { CP_ASYNC16(cdst[i] + bo, csrc[i]); csrc[i] += 32; }
            CP_COMMIT();
        }

        const uint32_t bofs = buf * 40960;
#pragma unroll
        for (int kk = 0; kk < 2; kk++) {
            const uint32_t ko = bofs + kk * 32;
            uint32_t ah[2][4], al[2][4];
#pragma unroll
            for (int mf = 0; mf < 2; mf++) {
                const uint32_t ao = a_base + mf * 1280 + ko;
                LDSM_X4(ah[mf][0], ah[mf][1], ah[mf][2], ah[mf][3], ao);
                LDSM_X4(al[mf][0], al[mf][1], al[mf][2], al[mf][3], ao + 10240);
            }
#pragma unroll
            for (int nf = 0; nf < 4; nf++) {
                uint32_t bh4[4], bl4[4];
                const uint32_t bo2 = b_base + nf * 1280 + ko;
                LDSM_X4(bh4[0], bh4[1], bh4[2], bh4[3], bo2);
                LDSM_X4(bl4[0], bl4[1], bl4[2], bl4[3], bo2 + 10240);
                // 12 MMAs, same-accumulator spacing = 4 (term-major interleave)
                MMA_BF16(acc[0][nf * 2 + 0], ah[0], bh4[0], bh4[1]);
                MMA_BF16(acc[1][nf * 2 + 0], ah[1], bh4[0], bh4[1]);
                MMA_BF16(acc[0][nf * 2 + 1], ah[0], bh4[2], bh4[3]);
                MMA_BF16(acc[1][nf * 2 + 1], ah[1], bh4[2], bh4[3]);
                MMA_BF16(acc[0][nf * 2 + 0], ah[0], bl4[0], bl4[1]);
                MMA_BF16(acc[1][nf * 2 + 0], ah[1], bl4[0], bl4[1]);
                MMA_BF16(acc[0][nf * 2 + 1], ah[0], bl4[2], bl4[3]);
                MMA_BF16(acc[1][nf * 2 + 1], ah[1], bl4[2], bl4[3]);
                MMA_BF16(acc[0][nf * 2 + 0], al[0], bh4[0], bh4[1]);
                MMA_BF16(acc[1][nf * 2 + 0], al[1], bh4[0], bh4[1]);
                MMA_BF16(acc[0][nf * 2 + 1], al[0], bh4[2], bh4[3]);
                MMA_BF16(acc[1][nf * 2 + 1], al[1], bh4[2], bh4[3]);
            }
        }
    }

    const int gid = lane >> 2, tig = lane & 3;
#pragma unroll
    for (int mf = 0; mf < 2; mf++) {
#pragma unroll
        for (int nf = 0; nf < 8; nf++) {
            const int col = n0 + wn * 64 + nf * 8 + tig * 2;
            const float bx0 = bias[col], bx1 = bias[col + 1];
            const int r0 = m0 + wm * 32 + mf * 16 + gid;
            float v00 = acc[mf][nf][0] + bx0, v01 = acc[mf][nf][1] + bx1;
            float v10 = acc[mf][nf][2] + bx0, v11 = acc[mf][nf][3] + bx1;
            if (MODE == 1) {
                float2 a0 = {v00, v01}, a1 = {v10, v11};
                *(float2*)&Cout[(long)r0 * N + col] = a0;
                *(float2*)&Cout[(long)(r0 + 8) * N + col] = a1;
            } else {
                uint32_t h0 = pack_bf16x2(v00, v01);
                uint32_t h1 = pack_bf16x2(v10, v11);
                float hf00 = __uint_as_float(h0 << 16);
                float hf01 = __uint_as_float(h0 & 0xffff0000u);
                float hf10 = __uint_as_float(h1 << 16);
                float hf11 = __uint_as_float(h1 & 0xffff0000u);
                uint32_t l0 = pack_bf16x2(v00 - hf00, v01 - hf01);
                uint32_t l1 = pack_bf16x2(v10 - hf10, v11 - hf11);
                *(uint32_t*)&g_qkvh[(long)r0 * N + col] = h0;
                *(uint32_t*)&g_qkvl[(long)r0 * N + col] = l0;
                *(uint32_t*)&g_qkvh[(long)(r0 + 8) * N + col] = h1;
                *(uint32_t*)&g_qkvl[(long)(r0 + 8) * N + col] = l1;
            }
        }
    }
}

// ============================================================================
// HMMA flash attention, causal, split hi/lo 3-MMA, pipelined K/V stages,
// dependency-spaced MMA issue order.
// ============================================================================
#define APITCH 144
#define SQ_BYTES  (128 * APITCH)          // 18432 (one of Qh/Ql)
#define SKV_BYTES (64 * APITCH)           // 9216  (one of Kh/Kl/Vh/Vl)
#define ATTN_SMEM (2*SQ_BYTES + 4*SKV_BYTES + 4*SKV_BYTES)   // 110592

__global__ __launch_bounds__(256, 2)
void attn_tc()
{
    extern __shared__ char smem[];
    const uint32_t sb = smem_to_u32(smem);
    const uint32_t sQ = sb;                          // Qh; Ql +18432
    const uint32_t sK0 = sb + 2 * SQ_BYTES;          // K buf: +buf*18432
    const uint32_t sV0 = sK0 + 4 * SKV_BYTES;        // V buf: +buf*18432

    const int qt = gridDim.x - 1 - blockIdx.x;   // long blocks first
    const int h  = blockIdx.y;
    const int b  = blockIdx.z;
    const int tid = threadIdx.x;
    const int wid = tid >> 5, lane = tid & 31;
    const int gid = lane >> 2, tig = lane & 3;
    const int q0 = qt * 128;
    const long rowbase = (long)b * SEQ;
    const int nk = 2 * qt + 2;

    // ---- Q tile load (group 1) ----
#pragma unroll
    for (int it = 0; it < 8; it++) {
        int g = it * 256 + tid;
        int sub = g >> 10, rem = g & 1023, row = rem >> 3, ch = rem & 7;
        const __nv_bfloat16* src = (sub ? g_qkvl : g_qkvh) +
            (rowbase + q0 + row) * D3 + h * HSZ + ch * 8;
        CP_ASYNC16(sQ + sub * SQ_BYTES + row * APITCH + ch * 16, src);
    }
    CP_COMMIT();

    // ---- K stage 0 load (group 2) ----
    {
#pragma unroll
        for (int it = 0; it < 4; it++) {
            int g = it * 256 + tid;
            int sub = g >> 9, rem = g & 511, row = rem >> 3, ch = rem & 7;
            const __nv_bfloat16* src = (sub ? g_qkvl : g_qkvh) +
                (rowbase + row) * D3 + EMB + h * HSZ + ch * 8;
            CP_ASYNC16(sK0 + sub * SKV_BYTES + row * APITCH + ch * 16, src);
        }
        CP_COMMIT();
    }

    const uint32_t a_base = sQ + (wid * 16 + (lane & 15)) * APITCH + (lane >> 4) * 16;
    const uint32_t bk_off = ((lane & 7) + ((lane >> 4) & 1) * 8) * APITCH
                              + ((lane >> 3) & 1) * 16;
    const uint32_t v_off = ((lane & 7) + ((lane >> 3) & 1) * 8) * APITCH
                              + (lane >> 4) * 16;

    float oacc[8][4];
#pragma unroll
    for (int df = 0; df < 8; df++)
#pragma unroll
        for (int q = 0; q < 4; q++) oacc[df][q] = 0.f;
    float mrow[2] = {-1e30f, -1e30f};
    float lrow[2] = {0.f, 0.f};

    const int qr0 = q0 + wid * 16 + gid;
    const int qr1 = qr0 + 8;

    for (int kt = 0; kt < nk; kt++) {
        const int k0 = kt * 64;
        const int buf = kt & 1;

        // ---- issue V_kt ----
        {
            const uint32_t vb = sV0 + buf * 2 * SKV_BYTES;
#pragma unroll
            for (int it = 0; it < 4; it++) {
                int g = it * 256 + tid;
                int sub = g >> 9, rem = g & 511, row = rem >> 3, ch = rem & 7;
                const __nv_bfloat16* src = (sub ? g_qkvl : g_qkvh) +
                    (rowbase + k0 + row) * D3 + 2 * EMB + h * HSZ + ch * 8;
                CP_ASYNC16(vb + sub * SKV_BYTES + row * APITCH + ch * 16, src);
            }
            CP_COMMIT();
        }
        // ---- issue K_{kt+1} (clamped re-load on last stage) ----
        {
            const int kn0 = (kt + 1 < nk) ? (kt + 1) * 64 : 0;
            const uint32_t kb = sK0 + (buf ^ 1) * 2 * SKV_BYTES;
#pragma unroll
            for (int it = 0; it < 4; it++) {
                int g = it * 256 + tid;
                int sub = g >> 9, rem = g & 511, row = rem >> 3, ch = rem & 7;
                const __nv_bfloat16* src = (sub ? g_qkvl : g_qkvh) +
                    (rowbase + kn0 + row) * D3 + EMB + h * HSZ + ch * 8;
                CP_ASYNC16(kb + sub * SKV_BYTES + row * APITCH + ch * 16, src);
            }
            CP_COMMIT();
        }

        CP_WAIT2();            // K_kt (and Q on kt=0) landed
        __syncthreads();

        // ---- QK^T scores (spacing-2 interleave) ----
        const uint32_t bk_base = sK0 + buf * 2 * SKV_BYTES + bk_off;
        float sacc[8][4];
#pragma unroll
        for (int nf = 0; nf < 8; nf++)
#pragma unroll
            for (int q = 0; q < 4; q++) sacc[nf][q] = 0.f;

#pragma unroll
        for (int ks = 0; ks < 4; ks++) {
            uint32_t ah[4], al[4];
            const uint32_t ao = a_base + ks * 32;
            LDSM_X4(ah[0], ah[1], ah[2], ah[3], ao);
            LDSM_X4(al[0], al[1], al[2], al[3], ao + SQ_BYTES);
#pragma unroll
            for (int nb = 0; nb < 4; nb++) {
                uint32_t bh4[4], bl4[4];
                const uint32_t bo = bk_base + nb * (16 * APITCH) + ks * 32;
                LDSM_X4(bh4[0], bh4[1], bh4[2], bh4[3], bo);
                LDSM_X4(bl4[0], bl4[1], bl4[2], bl4[3], bo + SKV_BYTES);
                MMA_BF16(sacc[nb * 2 + 0], ah, bh4[0], bh4[1]);
                MMA_BF16(sacc[nb * 2 + 1], ah, bh4[2], bh4[3]);
                MMA_BF16(sacc[nb * 2 + 0], ah, bl4[0], bl4[1]);
                MMA_BF16(sacc[nb * 2 + 1], ah, bl4[2], bl4[3]);
                MMA_BF16(sacc[nb * 2 + 0], al, bh4[0], bh4[1]);
                MMA_BF16(sacc[nb * 2 + 1], al, bh4[2], bh4[3]);
            }
        }

        CP_WAIT1();            // V_kt landed (K_{kt+1} still in flight)
        __syncthreads();

        // ---- scale + causal mask + row max ----
        const bool maskst = (kt >= 2 * qt);
        float tm0 = -1e30f, tm1 = -1e30f;
#pragma unroll
        for (int nf = 0; nf < 8; nf++) {
            const int c = k0 + nf * 8 + 2 * tig;
            float v0 = sacc[nf][0] * 0.125f;
            float v1 = sacc[nf][1] * 0.125f;
            float v2 = sacc[nf][2] * 0.125f;
            float v3 = sacc[nf][3] * 0.125f;
            if (maskst) {
                if (c     > qr0) v0 = -1e30f;
                if (c + 1 > qr0) v1 = -1e30f;
                if (c     > qr1) v2 = -1e30f;
                if (c + 1 > qr1) v3 = -1e30f;
            }
            sacc[nf][0] = v0; sacc[nf][1] = v1;
            sacc[nf][2] = v2; sacc[nf][3] = v3;
            tm0 = fmaxf(tm0, fmaxf(v0, v1));
            tm1 = fmaxf(tm1, fmaxf(v2, v3));
        }
        tm0 = fmaxf(tm0, __shfl_xor_sync(0xffffffffu, tm0, 1));
        tm0 = fmaxf(tm0, __shfl_xor_sync(0xffffffffu, tm0, 2));
        tm1 = fmaxf(tm1, __shfl_xor_sync(0xffffffffu, tm1, 1));
        tm1 = fmaxf(tm1, __shfl_xor_sync(0xffffffffu, tm1, 2));

        const float mn0 = fmaxf(mrow[0], tm0);
        const float mn1 = fmaxf(mrow[1], tm1);
        const float esc0 = __expf(mrow[0] - mn0);
        const float esc1 = __expf(mrow[1] - mn1);
        mrow[0] = mn0; mrow[1] = mn1;
#pragma unroll
        for (int df = 0; df < 8; df++) {
            oacc[df][0] *= esc0; oacc[df][1] *= esc0;
            oacc[df][2] *= esc1; oacc[df][3] *= esc1;
        }

        // ---- exp + row sums ----
        float ps0 = 0.f, ps1 = 0.f;
#pragma unroll
        for (int nf = 0; nf < 8; nf++) {
            float p0 = __expf(sacc[nf][0] - mn0);
            float p1 = __expf(sacc[nf][1] - mn0);
            float p2 = __expf(sacc[nf][2] - mn1);
            float p3 = __expf(sacc[nf][3] - mn1);
            ps0 += p0 + p1; ps1 += p2 + p3;
            sacc[nf][0] = p0; sacc[nf][1] = p1;
            sacc[nf][2] = p2; sacc[nf][3] = p3;
        }
        ps0 += __shfl_xor_sync(0xffffffffu, ps0, 1);
        ps0 += __shfl_xor_sync(0xffffffffu, ps0, 2);
        ps1 += __shfl_xor_sync(0xffffffffu, ps1, 1);
        ps1 += __shfl_xor_sync(0xffffffffu, ps1, 2);
        lrow[0] = lrow[0] * esc0 + ps0;
        lrow[1] = lrow[1] * esc1 + ps1;

        // ---- PV: repack P C-frags -> A-frags, MMA with V (spacing-2) ----
        const uint32_t v_base = sV0 + buf * 2 * SKV_BYTES + v_off;
#pragma unroll
        for (int ks = 0; ks < 4; ks++) {
            const int f0 = 2 * ks, f1 = 2 * ks + 1;
            uint32_t pah[4], pal[4];
            {
                uint32_t u;
                u = pack_bf16x2(sacc[f0][0], sacc[f0][1]); pah[0] = u;
                pal[0] = pack_bf16x2(sacc[f0][0] - __uint_as_float(u << 16),
                                     sacc[f0][1] - __uint_as_float(u & 0xffff0000u));
                u = pack_bf16x2(sacc[f0][2], sacc[f0][3]); pah[1] = u;
                pal[1] = pack_bf16x2(sacc[f0][2] - __uint_as_float(u << 16),
                                     sacc[f0][3] - __uint_as_float(u & 0xffff0000u));
                u = pack_bf16x2(sacc[f1][0], sacc[f1][1]); pah[2] = u;
                pal[2] = pack_bf16x2(sacc[f1][0] - __uint_as_float(u << 16),
                                     sacc[f1][1] - __uint_as_float(u & 0xffff0000u));
                u = pack_bf16x2(sacc[f1][2], sacc[f1][3]); pah[3] = u;
                pal[3] = pack_bf16x2(sacc[f1][2] - __uint_as_float(u << 16),
                                     sacc[f1][3] - __uint_as_float(u & 0xffff0000u));
            }
#pragma unroll
            for (int nb = 0; nb < 4; nb++) {
                uint32_t vh4[4], vl4[4];
                const uint32_t vo = v_base + ks * (16 * APITCH) + nb * 32;
                LDSM_X4T(vh4[0], vh4[1], vh4[2], vh4[3], vo);
                LDSM_X4T(vl4[0], vl4[1], vl4[2], vl4[3], vo + SKV_BYTES);
                MMA_BF16(oacc[nb * 2 + 0], pah, vh4[0], vh4[1]);
                MMA_BF16(oacc[nb * 2 + 1], pah, vh4[2], vh4[3]);
                MMA_BF16(oacc[nb * 2 + 0], pah, vl4[0], vl4[1]);
                MMA_BF16(oacc[nb * 2 + 1], pah, vl4[2], vl4[3]);
                MMA_BF16(oacc[nb * 2 + 0], pal, vh4[0], vh4[1]);
                MMA_BF16(oacc[nb * 2 + 1], pal, vh4[2], vh4[3]);
            }
        }
    }

    // ---- finalize: O = oacc/l, split hi/lo, write g_oh/g_ol ----
    const float inv0 = 1.f / lrow[0];
    const float inv1 = 1.f / lrow[1];
#pragma unroll
    for (int df = 0; df < 8; df++) {
        const int col = h * HSZ + df * 8 + 2 * tig;
        float v00 = oacc[df][0] * inv0, v01 = oacc[df][1] * inv0;
        float v10 = oacc[df][2] * inv1, v11 = oacc[df][3] * inv1;
        uint32_t h0 = pack_bf16x2(v00, v01);
        uint32_t h1 = pack_bf16x2(v10, v11);
        uint32_t l0 = pack_bf16x2(v00 - __uint_as_float(h0 << 16),
                                  v01 - __uint_as_float(h0 & 0xffff0000u));
        uint32_t l1 = pack_bf16x2(v10 - __uint_as_float(h1 << 16),
                                  v11 - __uint_as_float(h1 & 0xffff0000u));
        *(uint32_t*)&g_oh[(rowbase + qr0) * EMB + col] = h0;
        *(uint32_t*)&g_ol[(rowbase + qr0) * EMB + col] = l0;
        *(uint32_t*)&g_oh[(rowbase + qr1) * EMB + col] = h1;
        *(uint32_t*)&g_ol[(rowbase + qr1) * EMB + col] = l1;
    }
}

// ---------------------------------------------------------------------------
extern "C" void kernel_launch(void* const* d_in, const int* in_sizes, int n_in,
                              void* d_out, int out_size)
{
    const float* x     = (const float*)d_in[0];
    const float* W_qkv = (const float*)d_in[1];
    const float* b_qkv = (const float*)d_in[2];
    const float* W_out = (const float*)d_in[3];
    const float* b_out = (const float*)d_in[4];
    float* out = (float*)d_out;

    // 0) weight transpose + split; x split
    prep_wt<0><<<dim3(D3 / 32, EMB / 32), dim3(32, 8)>>>(W_qkv, EMB, D3);
    prep_wt<1><<<dim3(EMB / 32, EMB / 32), dim3(32, 8)>>>(W_out, EMB, EMB);
    prep_split_x<<<ROWS * EMB / 4 / 256, 256>>>(x);

    // 1) QKV projection (HMMA), emits bf16 hi/lo qkv
    cudaFuncSetAttribute(gemm_tc<0>, cudaFuncAttributeMaxDynamicSharedMemorySize, GEMM_SMEM);
    gemm_tc<0><<<dim3(D3 / 128, ROWS / 128), 256, GEMM_SMEM>>>(b_qkv, nullptr);

    // 2) causal flash attention (HMMA), emits bf16 hi/lo O
    cudaFuncSetAttribute(attn_tc, cudaFuncAttributeMaxDynamicSharedMemorySize, ATTN_SMEM);
    attn_tc<<<dim3(SEQ / 128, NH, BATCH), 256, ATTN_SMEM>>>();

    // 3) output projection (HMMA), fp32 out + bias
    cudaFuncSetAttribute(gemm_tc<1>, cudaFuncAttributeMaxDynamicSharedMemorySize, GEMM_SMEM);
    gemm_tc<1><<<dim3(EMB / 128, ROWS / 128), 256, GEMM_SMEM>>>(b_out, out);
}

// round 10
// speedup vs baseline: 1.4994x; 1.4994x over previous
#include <cuda_runtime.h>
#include <cuda_fp16.h>
#include <cstdint>

#define SEQ   2048
#define EMB   1024
#define NH    16
#define HSZ   64
#define BATCH 2
#define ROWS  (BATCH * SEQ)     // 4096
#define D3    (3 * EMB)         // 3072
#define NCK   (EMB / 32)        // 32 k-stages of BK=32 for projection GEMMs

// Scratch (device globals — no allocation allowed)
__device__ __half g_qkvh[ROWS * D3];   // qkv hi (single fp16 for K,V; hi for Q)
__device__ __half g_qlo[ROWS * EMB];   // Q lo residual only
__device__ __half g_wt1[D3 * EMB];     // W_qkv^T fp16 [3072,1024] (K-major)
__device__ __half g_wt2[EMB * EMB];    // W_out^T fp16
__device__ __half g_xh[ROWS * EMB];    // x hi/lo
__device__ __half g_xl[ROWS * EMB];
__device__ __half g_oh[ROWS * EMB];    // attn-out hi/lo
__device__ __half g_ol[ROWS * EMB];

// ============================================================================
// asm helpers (plain sm_80+ PTX — legal on target sm_103)
// ============================================================================
__device__ __forceinline__ uint32_t smem_to_u32(const void* p) {
    uint32_t a;
    asm("{ .reg .u64 t; cvta.to.shared.u64 t, %1; cvt.u32.u64 %0, t; }"
        : "=r"(a) : "l"(p));
    return a;
}

#define CP_ASYNC16(dst, src) \
    asm volatile("cp.async.cg.shared.global [%0], [%1], 16;" \
                 :: "r"(dst), "l"(__cvta_generic_to_global(src)) : "memory")
#define CP_COMMIT() asm volatile("cp.async.commit_group;" ::: "memory")
#define CP_WAIT0()  asm volatile("cp.async.wait_group 0;" ::: "memory")
#define CP_WAIT1()  asm volatile("cp.async.wait_group 1;" ::: "memory")
#define CP_WAIT2()  asm volatile("cp.async.wait_group 2;" ::: "memory")

#define LDSM_X4(r0, r1, r2, r3, addr) \
    asm volatile("ldmatrix.sync.aligned.m8n8.x4.shared.b16 {%0,%1,%2,%3}, [%4];" \
                 : "=r"(r0), "=r"(r1), "=r"(r2), "=r"(r3) : "r"(addr))
#define LDSM_X4T(r0, r1, r2, r3, addr) \
    asm volatile("ldmatrix.sync.aligned.m8n8.x4.trans.shared.b16 {%0,%1,%2,%3}, [%4];" \
                 : "=r"(r0), "=r"(r1), "=r"(r2), "=r"(r3) : "r"(addr))

#define MMA_F16(d, a, b0v, b1v) \
    asm volatile("mma.sync.aligned.m16n8k16.row.col.f32.f16.f16.f32 " \
                 "{%0,%1,%2,%3}, {%4,%5,%6,%7}, {%8,%9}, {%0,%1,%2,%3};" \
                 : "+f"((d)[0]), "+f"((d)[1]), "+f"((d)[2]), "+f"((d)[3]) \
                 : "r"((a)[0]), "r"((a)[1]), "r"((a)[2]), "r"((a)[3]), \
                   "r"(b0v), "r"(b1v))

// pack two f32 -> f16x2 (first arg in low half)
__device__ __forceinline__ uint32_t pack_f16x2(float lo, float hi) {
    uint32_t r;
    asm("cvt.rn.f16x2.f32 %0, %1, %2;" : "=r"(r) : "f"(hi), "f"(lo));
    return r;
}
__device__ __forceinline__ float2 unpack_f16x2(uint32_t u) {
    __half2 h2 = *reinterpret_cast<__half2*>(&u);
    return __half22float2(h2);
}

// ============================================================================
// Prep: Wt[n][k] = W[k][n], single fp16. W is [K, N] row-major.
// ============================================================================
template <int MODE>
__global__ void prep_wt(const float* __restrict__ W, int K, int N)
{
    __half* Wt = (MODE == 0) ? g_wt1 : g_wt2;
    __shared__ float t[32][33];
    const int n0 = blockIdx.x * 32, k0 = blockIdx.y * 32;
    const int tx = threadIdx.x, ty = threadIdx.y;
#pragma unroll
    for (int j = 0; j < 32; j += 8)
        t[ty + j][tx] = W[(long)(k0 + ty + j) * N + n0 + tx];
    __syncthreads();
#pragma unroll
    for (int j = 0; j < 32; j += 8) {
        const int n = n0 + ty + j, k = k0 + tx;
        Wt[(long)n * K + k] = __float2half_rn(t[tx][ty + j]);
    }
}

// x -> g_xh/g_xl (elementwise fp16 hi/lo split)
__global__ void prep_split_x(const float* __restrict__ s)
{
    const int i = blockIdx.x * blockDim.x + threadIdx.x;   // float4 index
    float4 v = ((const float4*)s)[i];
    union { __half b[4]; uint2 u; } ph, pl;
    ph.b[0] = __float2half_rn(v.x);
    ph.b[1] = __float2half_rn(v.y);
    ph.b[2] = __float2half_rn(v.z);
    ph.b[3] = __float2half_rn(v.w);
    pl.b[0] = __float2half_rn(v.x - __half2float(ph.b[0]));
    pl.b[1] = __float2half_rn(v.y - __half2float(ph.b[1]));
    pl.b[2] = __float2half_rn(v.z - __half2float(ph.b[2]));
    pl.b[3] = __float2half_rn(v.w - __half2float(ph.b[3]));
    ((uint2*)g_xh)[i] = ph.u;
    ((uint2*)g_xl)[i] = pl.u;
}

// ============================================================================
// HMMA GEMM + bias. 2-MMA scheme: A split hi/lo fp16, B single fp16.
// CTA 128x128, BK=32, 8 warps (4m x 2n). Single __syncthreads per k-stage.
// MODE 0: A=g_xh/l, B=g_wt1, writes g_qkvh (hi) + g_qlo (Q-region lo)
// MODE 1: A=g_oh/l, B=g_wt2, writes fp32 Cout (+bias)
// smem per buffer: Ah(10240) Al(10240) B(10240) = 30720; x2 = 61440
// ============================================================================
#define GEMM_SMEM 61440

template <int MODE>
__global__ __launch_bounds__(256, 2)
void gemm_tc(const float* __restrict__ bias, float* __restrict__ Cout)
{
    const __half* Ah = (MODE == 0) ? g_xh : g_oh;
    const __half* Al = (MODE == 0) ? g_xl : g_ol;
    const __half* Bw = (MODE == 0) ? g_wt1 : g_wt2;
    const int N = (MODE == 0) ? D3 : EMB;
    const int K = EMB;

    extern __shared__ char smem[];
    const uint32_t sb = smem_to_u32(smem);
    const int tid = threadIdx.x;
    const int wid = tid >> 5, lane = tid & 31;
    const int wm = wid & 3, wn = wid >> 2;
    const int m0 = blockIdx.y * 128, n0 = blockIdx.x * 128;

    // 6 x 16B cp.async chunks per thread per stage (3 streams x 512 chunks)
    const __half* csrc[6];
    uint32_t cdst[6];
#pragma unroll
    for (int i = 0; i < 6; i++) {
        int g = i * 256 + tid;
        int sub = g >> 9, c = g & 511, row = c >> 2, ch = c & 3;
        const __half* bp =
            (sub == 0) ? Ah + (long)m0 * K :
            (sub == 1) ? Al + (long)m0 * K :
                         Bw + (long)n0 * K;
        csrc[i] = bp + (long)row * K + ch * 8;
        cdst[i] = sb + sub * 10240 + row * 80 + ch * 16;
    }

#pragma unroll
    for (int i = 0; i < 6; i++) { CP_ASYNC16(cdst[i], csrc[i]); csrc[i] += 32; }
    CP_COMMIT();

    const uint32_t a_base = sb + (wm * 32 + (lane & 15)) * 80 + (lane >> 4) * 16;
    const uint32_t b_base = sb + 20480 +
        (wn * 64 + (lane & 7) + ((lane >> 4) & 1) * 8) * 80 + ((lane >> 3) & 1) * 16;

    float acc[2][8][4];
#pragma unroll
    for (int mf = 0; mf < 2; mf++)
#pragma unroll
        for (int nf = 0; nf < 8; nf++)
#pragma unroll
            for (int q = 0; q < 4; q++) acc[mf][nf][q] = 0.f;

    for (int ck = 0; ck < NCK; ck++) {
        const int buf = ck & 1;
        CP_WAIT0();
        __syncthreads();
        if (ck + 1 < NCK) {
            const uint32_t bo = (buf ^ 1) * 30720;
#pragma unroll
            for (int i = 0; i < 6; i++) { CP_ASYNC16(cdst[i] + bo, csrc[i]); csrc[i] += 32; }
            CP_COMMIT();
        }

        const uint32_t bofs = buf * 30720;
#pragma unroll
        for (int kk = 0; kk < 2; kk++) {
            const uint32_t ko = bofs + kk * 32;
            uint32_t ah[2][4], al[2][4];
#pragma unroll
            for (int mf = 0; mf < 2; mf++) {
                const uint32_t ao = a_base + mf * 1280 + ko;
                LDSM_X4(ah[mf][0], ah[mf][1], ah[mf][2], ah[mf][3], ao);
                LDSM_X4(al[mf][0], al[mf][1], al[mf][2], al[mf][3], ao + 10240);
            }
#pragma unroll
            for (int nf = 0; nf < 4; nf++) {
                uint32_t b4[4];
                LDSM_X4(b4[0], b4[1], b4[2], b4[3], b_base + nf * 1280 + ko);
                // 8 MMAs, same-accumulator spacing = 4
                MMA_F16(acc[0][nf * 2 + 0], ah[0], b4[0], b4[1]);
                MMA_F16(acc[1][nf * 2 + 0], ah[1], b4[0], b4[1]);
                MMA_F16(acc[0][nf * 2 + 1], ah[0], b4[2], b4[3]);
                MMA_F16(acc[1][nf * 2 + 1], ah[1], b4[2], b4[3]);
                MMA_F16(acc[0][nf * 2 + 0], al[0], b4[0], b4[1]);
                MMA_F16(acc[1][nf * 2 + 0], al[1], b4[0], b4[1]);
                MMA_F16(acc[0][nf * 2 + 1], al[0], b4[2], b4[3]);
                MMA_F16(acc[1][nf * 2 + 1], al[1], b4[2], b4[3]);
            }
        }
    }

    const int gid = lane >> 2, tig = lane & 3;
#pragma unroll
    for (int mf = 0; mf < 2; mf++) {
#pragma unroll
        for (int nf = 0; nf < 8; nf++) {
            const int col = n0 + wn * 64 + nf * 8 + tig * 2;
            const float bx0 = bias[col], bx1 = bias[col + 1];
            const int r0 = m0 + wm * 32 + mf * 16 + gid;
            float v00 = acc[mf][nf][0] + bx0, v01 = acc[mf][nf][1] + bx1;
            float v10 = acc[mf][nf][2] + bx0, v11 = acc[mf][nf][3] + bx1;
            if (MODE == 1) {
                float2 a0 = {v00, v01}, a1 = {v10, v11};
                *(float2*)&Cout[(long)r0 * N + col] = a0;
                *(float2*)&Cout[(long)(r0 + 8) * N + col] = a1;
            } else {
                uint32_t h0 = pack_f16x2(v00, v01);
                uint32_t h1 = pack_f16x2(v10, v11);
                *(uint32_t*)&g_qkvh[(long)r0 * N + col] = h0;
                *(uint32_t*)&g_qkvh[(long)(r0 + 8) * N + col] = h1;
                if (n0 < EMB) {   // Q region: also store lo residual
                    float2 f0 = unpack_f16x2(h0), f1 = unpack_f16x2(h1);
                    uint32_t l0 = pack_f16x2(v00 - f0.x, v01 - f0.y);
                    uint32_t l1 = pack_f16x2(v10 - f1.x, v11 - f1.y);
                    *(uint32_t*)&g_qlo[(long)r0 * EMB + col] = l0;
                    *(uint32_t*)&g_qlo[(long)(r0 + 8) * EMB + col] = l1;
                }
            }
        }
    }
}

// ============================================================================
// HMMA flash attention, causal. Q split hi/lo fp16 (A operand); K,V single
// fp16 (B operand). 2-MMA scheme. Pipelined K/V double-buffer stages.
// Q tile 128 x K tile 64, hs=64, 256 threads (8 warps x 16 q-rows).
// ============================================================================
#define APITCH 144
#define SQ_BYTES  (128 * APITCH)          // 18432 (one of Qh/Ql)
#define SKV_BYTES (64 * APITCH)           // 9216  (one of K/V per buffer)
#define ATTN_SMEM (2*SQ_BYTES + 2*SKV_BYTES + 2*SKV_BYTES)   // 73728

__global__ __launch_bounds__(256, 2)
void attn_tc()
{
    extern __shared__ char smem[];
    const uint32_t sb = smem_to_u32(smem);
    const uint32_t sQ = sb;                          // Qh; Ql +18432
    const uint32_t sK0 = sb + 2 * SQ_BYTES;          // K bufs: +buf*9216
    const uint32_t sV0 = sK0 + 2 * SKV_BYTES;        // V bufs: +buf*9216

    const int qt = gridDim.x - 1 - blockIdx.x;   // long blocks first
    const int h  = blockIdx.y;
    const int b  = blockIdx.z;
    const int tid = threadIdx.x;
    const int wid = tid >> 5, lane = tid & 31;
    const int gid = lane >> 2, tig = lane & 3;
    const int q0 = qt * 128;
    const long rowbase = (long)b * SEQ;
    const int nk = 2 * qt + 2;

    // ---- Q tile load (group 1): hi + lo ----
#pragma unroll
    for (int it = 0; it < 8; it++) {
        int g = it * 256 + tid;
        int sub = g >> 10, rem = g & 1023, row = rem >> 3, ch = rem & 7;
        const __half* src = sub
            ? g_qlo  + (rowbase + q0 + row) * EMB + h * HSZ + ch * 8
            : g_qkvh + (rowbase + q0 + row) * D3  + h * HSZ + ch * 8;
        CP_ASYNC16(sQ + sub * SQ_BYTES + row * APITCH + ch * 16, src);
    }
    CP_COMMIT();

    // ---- K stage 0 load (group 2) ----
#pragma unroll
    for (int it = 0; it < 2; it++) {
        int g = it * 256 + tid;
        int row = g >> 3, ch = g & 7;
        const __half* src = g_qkvh + (rowbase + row) * D3 + EMB + h * HSZ + ch * 8;
        CP_ASYNC16(sK0 + row * APITCH + ch * 16, src);
    }
    CP_COMMIT();

    const uint32_t a_base = sQ + (wid * 16 + (lane & 15)) * APITCH + (lane >> 4) * 16;
    const uint32_t bk_off = ((lane & 7) + ((lane >> 4) & 1) * 8) * APITCH
                              + ((lane >> 3) & 1) * 16;
    const uint32_t v_off = ((lane & 7) + ((lane >> 3) & 1) * 8) * APITCH
                              + (lane >> 4) * 16;

    float oacc[8][4];
#pragma unroll
    for (int df = 0; df < 8; df++)
#pragma unroll
        for (int q = 0; q < 4; q++) oacc[df][q] = 0.f;
    float mrow[2] = {-1e30f, -1e30f};
    float lrow[2] = {0.f, 0.f};

    const int qr0 = q0 + wid * 16 + gid;
    const int qr1 = qr0 + 8;

    for (int kt = 0; kt < nk; kt++) {
        const int k0 = kt * 64;
        const int buf = kt & 1;

        // ---- issue V_kt ----
#pragma unroll
        for (int it = 0; it < 2; it++) {
            int g = it * 256 + tid;
            int row = g >> 3, ch = g & 7;
            const __half* src = g_qkvh + (rowbase + k0 + row) * D3
                                + 2 * EMB + h * HSZ + ch * 8;
            CP_ASYNC16(sV0 + buf * SKV_BYTES + row * APITCH + ch * 16, src);
        }
        CP_COMMIT();
        // ---- issue K_{kt+1} (clamped re-load on last stage) ----
        {
            const int kn0 = (kt + 1 < nk) ? (kt + 1) * 64 : 0;
#pragma unroll
            for (int it = 0; it < 2; it++) {
                int g = it * 256 + tid;
                int row = g >> 3, ch = g & 7;
                const __half* src = g_qkvh + (rowbase + kn0 + row) * D3
                                    + EMB + h * HSZ + ch * 8;
                CP_ASYNC16(sK0 + (buf ^ 1) * SKV_BYTES + row * APITCH + ch * 16, src);
            }
            CP_COMMIT();
        }

        CP_WAIT2();            // K_kt (and Q on kt=0) landed
        __syncthreads();

        // ---- QK^T scores ----
        const uint32_t bk_base = sK0 + buf * SKV_BYTES + bk_off;
        float sacc[8][4];
#pragma unroll
        for (int nf = 0; nf < 8; nf++)
#pragma unroll
            for (int q = 0; q < 4; q++) sacc[nf][q] = 0.f;

#pragma unroll
        for (int ks = 0; ks < 4; ks++) {
            uint32_t qh[4], ql[4];
            const uint32_t ao = a_base + ks * 32;
            LDSM_X4(qh[0], qh[1], qh[2], qh[3], ao);
            LDSM_X4(ql[0], ql[1], ql[2], ql[3], ao + SQ_BYTES);
#pragma unroll
            for (int nb = 0; nb < 4; nb++) {
                uint32_t k4[4];
                LDSM_X4(k4[0], k4[1], k4[2], k4[3],
                        bk_base + nb * (16 * APITCH) + ks * 32);
                MMA_F16(sacc[nb * 2 + 0], qh, k4[0], k4[1]);
                MMA_F16(sacc[nb * 2 + 1], qh, k4[2], k4[3]);
                MMA_F16(sacc[nb * 2 + 0], ql, k4[0], k4[1]);
                MMA_F16(sacc[nb * 2 + 1], ql, k4[2], k4[3]);
            }
        }

        CP_WAIT1();            // V_kt landed (K_{kt+1} still in flight)
        __syncthreads();

        // ---- scale + causal mask + row max ----
        const bool maskst = (kt >= 2 * qt);
        float tm0 = -1e30f, tm1 = -1e30f;
#pragma unroll
        for (int nf = 0; nf < 8; nf++) {
            const int c = k0 + nf * 8 + 2 * tig;
            float v0 = sacc[nf][0] * 0.125f;
            float v1 = sacc[nf][1] * 0.125f;
            float v2 = sacc[nf][2] * 0.125f;
            float v3 = sacc[nf][3] * 0.125f;
            if (maskst) {
                if (c     > qr0) v0 = -1e30f;
                if (c + 1 > qr0) v1 = -1e30f;
                if (c     > qr1) v2 = -1e30f;
                if (c + 1 > qr1) v3 = -1e30f;
            }
            sacc[nf][0] = v0; sacc[nf][1] = v1;
            sacc[nf][2] = v2; sacc[nf][3] = v3;
            tm0 = fmaxf(tm0, fmaxf(v0, v1));
            tm1 = fmaxf(tm1, fmaxf(v2, v3));
        }
        tm0 = fmaxf(tm0, __shfl_xor_sync(0xffffffffu, tm0, 1));
        tm0 = fmaxf(tm0, __shfl_xor_sync(0xffffffffu, tm0, 2));
        tm1 = fmaxf(tm1, __shfl_xor_sync(0xffffffffu, tm1, 1));
        tm1 = fmaxf(tm1, __shfl_xor_sync(0xffffffffu, tm1, 2));

        const float mn0 = fmaxf(mrow[0], tm0);
        const float mn1 = fmaxf(mrow[1], tm1);
        const float esc0 = __expf(mrow[0] - mn0);
        const float esc1 = __expf(mrow[1] - mn1);
        mrow[0] = mn0; mrow[1] = mn1;
#pragma unroll
        for (int df = 0; df < 8; df++) {
            oacc[df][0] *= esc0; oacc[df][1] *= esc0;
            oacc[df][2] *= esc1; oacc[df][3] *= esc1;
        }

        // ---- exp + row sums ----
        float ps0 = 0.f, ps1 = 0.f;
#pragma unroll
        for (int nf = 0; nf < 8; nf++) {
            float p0 = __expf(sacc[nf][0] - mn0);
            float p1 = __expf(sacc[nf][1] - mn0);
            float p2 = __expf(sacc[nf][2] - mn1);
            float p3 = __expf(sacc[nf][3] - mn1);
            ps0 += p0 + p1; ps1 += p2 + p3;
            sacc[nf][0] = p0; sacc[nf][1] = p1;
            sacc[nf][2] = p2; sacc[nf][3] = p3;
        }
        ps0 += __shfl_xor_sync(0xffffffffu, ps0, 1);
        ps0 += __shfl_xor_sync(0xffffffffu, ps0, 2);
        ps1 += __shfl_xor_sync(0xffffffffu, ps1, 1);
        ps1 += __shfl_xor_sync(0xffffffffu, ps1, 2);
        lrow[0] = lrow[0] * esc0 + ps0;
        lrow[1] = lrow[1] * esc1 + ps1;

        // ---- PV: repack P C-frags -> A-frags (hi/lo fp16), MMA with V ----
        const uint32_t v_base = sV0 + buf * SKV_BYTES + v_off;
#pragma unroll
        for (int ks = 0; ks < 4; ks++) {
            const int f0 = 2 * ks, f1 = 2 * ks + 1;
            uint32_t pah[4], pal[4];
            {
                uint32_t u; float2 f;
                u = pack_f16x2(sacc[f0][0], sacc[f0][1]); pah[0] = u;
                f = unpack_f16x2(u);
                pal[0] = pack_f16x2(sacc[f0][0] - f.x, sacc[f0][1] - f.y);
                u = pack_f16x2(sacc[f0][2], sacc[f0][3]); pah[1] = u;
                f = unpack_f16x2(u);
                pal[1] = pack_f16x2(sacc[f0][2] - f.x, sacc[f0][3] - f.y);
                u = pack_f16x2(sacc[f1][0], sacc[f1][1]); pah[2] = u;
                f = unpack_f16x2(u);
                pal[2] = pack_f16x2(sacc[f1][0] - f.x, sacc[f1][1] - f.y);
                u = pack_f16x2(sacc[f1][2], sacc[f1][3]); pah[3] = u;
                f = unpack_f16x2(u);
                pal[3] = pack_f16x2(sacc[f1][2] - f.x, sacc[f1][3] - f.y);
            }
#pragma unroll
            for (int nb = 0; nb < 4; nb++) {
                uint32_t v4[4];
                LDSM_X4T(v4[0], v4[1], v4[2], v4[3],
                         v_base + ks * (16 * APITCH) + nb * 32);
                MMA_F16(oacc[nb * 2 + 0], pah, v4[0], v4[1]);
                MMA_F16(oacc[nb * 2 + 1], pah, v4[2], v4[3]);
                MMA_F16(oacc[nb * 2 + 0], pal, v4[0], v4[1]);
                MMA_F16(oacc[nb * 2 + 1], pal, v4[2], v4[3]);
            }
        }
    }

    // ---- finalize: O = oacc/l, split fp16 hi/lo, write g_oh/g_ol ----
    const float inv0 = 1.f / lrow[0];
    const float inv1 = 1.f / lrow[1];
#pragma unroll
    for (int df = 0; df < 8; df++) {
        const int col = h * HSZ + df * 8 + 2 * tig;
        float v00 = oacc[df][0] * inv0, v01 = oacc[df][1] * inv0;
        float v10 = oacc[df][2] * inv1, v11 = oacc[df][3] * inv1;
        uint32_t h0 = pack_f16x2(v00, v01);
        uint32_t h1 = pack_f16x2(v10, v11);
        float2 f0 = unpack_f16x2(h0), f1 = unpack_f16x2(h1);
        uint32_t l0 = pack_f16x2(v00 - f0.x, v01 - f0.y);
        uint32_t l1 = pack_f16x2(v10 - f1.x, v11 - f1.y);
        *(uint32_t*)&g_oh[(rowbase + qr0) * EMB + col] = h0;
        *(uint32_t*)&g_ol[(rowbase + qr0) * EMB + col] = l0;
        *(uint32_t*)&g_oh[(rowbase + qr1) * EMB + col] = h1;
        *(uint32_t*)&g_ol[(rowbase + qr1) * EMB + col] = l1;
    }
}

// ---------------------------------------------------------------------------
extern "C" void kernel_launch(void* const* d_in, const int* in_sizes, int n_in,
                              void* d_out, int out_size)
{
    const float* x     = (const float*)d_in[0];
    const float* W_qkv = (const float*)d_in[1];
    const float* b_qkv = (const float*)d_in[2];
    const float* W_out = (const float*)d_in[3];
    const float* b_out = (const float*)d_in[4];
    float* out = (float*)d_out;

    // 0) weight transpose (fp16); x hi/lo split
    prep_wt<0><<<dim3(D3 / 32, EMB / 32), dim3(32, 8)>>>(W_qkv, EMB, D3);
    prep_wt<1><<<dim3(EMB / 32, EMB / 32), dim3(32, 8)>>>(W_out, EMB, EMB);
    prep_split_x<<<ROWS * EMB / 4 / 256, 256>>>(x);

    // 1) QKV projection (HMMA fp16 2-MMA)
    cudaFuncSetAttribute(gemm_tc<0>, cudaFuncAttributeMaxDynamicSharedMemorySize, GEMM_SMEM);
    gemm_tc<0><<<dim3(D3 / 128, ROWS / 128), 256, GEMM_SMEM>>>(b_qkv, nullptr);

    // 2) causal flash attention (HMMA fp16 2-MMA)
    cudaFuncSetAttribute(attn_tc, cudaFuncAttributeMaxDynamicSharedMemorySize, ATTN_SMEM);
    attn_tc<<<dim3(SEQ / 128, NH, BATCH), 256, ATTN_SMEM>>>();

    // 3) output projection (HMMA fp16 2-MMA), fp32 out + bias
    cudaFuncSetAttribute(gemm_tc<1>, cudaFuncAttributeMaxDynamicSharedMemorySize, GEMM_SMEM);
    gemm_tc<1><<<dim3(EMB / 128, ROWS / 128), 256, GEMM_SMEM>>>(b_out, out);
}

// round 11
// speedup vs baseline: 2.2807x; 1.5211x over previous
#include <cuda_runtime.h>
#include <cuda_fp16.h>
#include <cstdint>

#define SEQ   2048
#define EMB   1024
#define NH    16
#define HSZ   64
#define BATCH 2
#define ROWS  (BATCH * SEQ)     // 4096
#define D3    (3 * EMB)         // 3072
#define NCK   (EMB / 32)        // 32 k-stages of BK=32 for projection GEMMs

// Scratch (device globals — no allocation allowed)
__device__ __half g_qkv[ROWS * D3];    // qkv fp16 [b*s][3*EMB]
__device__ __half g_wt1[D3 * EMB];     // W_qkv^T fp16 [3072,1024] (K-major)
__device__ __half g_wt2[EMB * EMB];    // W_out^T fp16
__device__ __half g_x[ROWS * EMB];     // x fp16
__device__ __half g_o[ROWS * EMB];     // attn-out fp16

// ============================================================================
// asm helpers (plain sm_80+ PTX — legal on target sm_103)
// ============================================================================
__device__ __forceinline__ uint32_t smem_to_u32(const void* p) {
    uint32_t a;
    asm("{ .reg .u64 t; cvta.to.shared.u64 t, %1; cvt.u32.u64 %0, t; }"
        : "=r"(a) : "l"(p));
    return a;
}

#define CP_ASYNC16(dst, src) \
    asm volatile("cp.async.cg.shared.global [%0], [%1], 16;" \
                 :: "r"(dst), "l"(__cvta_generic_to_global(src)) : "memory")
#define CP_COMMIT() asm volatile("cp.async.commit_group;" ::: "memory")
#define CP_WAIT0()  asm volatile("cp.async.wait_group 0;" ::: "memory")
#define CP_WAIT1()  asm volatile("cp.async.wait_group 1;" ::: "memory")
#define CP_WAIT2()  asm volatile("cp.async.wait_group 2;" ::: "memory")

#define LDSM_X4(r0, r1, r2, r3, addr) \
    asm volatile("ldmatrix.sync.aligned.m8n8.x4.shared.b16 {%0,%1,%2,%3}, [%4];" \
                 : "=r"(r0), "=r"(r1), "=r"(r2), "=r"(r3) : "r"(addr))
#define LDSM_X4T(r0, r1, r2, r3, addr) \
    asm volatile("ldmatrix.sync.aligned.m8n8.x4.trans.shared.b16 {%0,%1,%2,%3}, [%4];" \
                 : "=r"(r0), "=r"(r1), "=r"(r2), "=r"(r3) : "r"(addr))

#define MMA_F16(d, a, b0v, b1v) \
    asm volatile("mma.sync.aligned.m16n8k16.row.col.f32.f16.f16.f32 " \
                 "{%0,%1,%2,%3}, {%4,%5,%6,%7}, {%8,%9}, {%0,%1,%2,%3};" \
                 : "+f"((d)[0]), "+f"((d)[1]), "+f"((d)[2]), "+f"((d)[3]) \
                 : "r"((a)[0]), "r"((a)[1]), "r"((a)[2]), "r"((a)[3]), \
                   "r"(b0v), "r"(b1v))

// pack two f32 -> f16x2 (first arg in low half)
__device__ __forceinline__ uint32_t pack_f16x2(float lo, float hi) {
    uint32_t r;
    asm("cvt.rn.f16x2.f32 %0, %1, %2;" : "=r"(r) : "f"(hi), "f"(lo));
    return r;
}

// ============================================================================
// Prep: Wt[n][k] = W[k][n], single fp16. W is [K, N] row-major.
// ============================================================================
template <int MODE>
__global__ void prep_wt(const float* __restrict__ W, int K, int N)
{
    __half* Wt = (MODE == 0) ? g_wt1 : g_wt2;
    __shared__ float t[32][33];
    const int n0 = blockIdx.x * 32, k0 = blockIdx.y * 32;
    const int tx = threadIdx.x, ty = threadIdx.y;
#pragma unroll
    for (int j = 0; j < 32; j += 8)
        t[ty + j][tx] = W[(long)(k0 + ty + j) * N + n0 + tx];
    __syncthreads();
#pragma unroll
    for (int j = 0; j < 32; j += 8) {
        const int n = n0 + ty + j, k = k0 + tx;
        Wt[(long)n * K + k] = __float2half_rn(t[tx][ty + j]);
    }
}

// x -> g_x (fp16 convert)
__global__ void prep_x(const float* __restrict__ s)
{
    const int i = blockIdx.x * blockDim.x + threadIdx.x;   // float4 index
    float4 v = ((const float4*)s)[i];
    uint2 u;
    u.x = pack_f16x2(v.x, v.y);
    u.y = pack_f16x2(v.z, v.w);
    ((uint2*)g_x)[i] = u;
}

// ============================================================================
// HMMA GEMM + bias, single fp16. CTA 128x128, BK=32, 8 warps (4m x 2n).
// Single __syncthreads per k-stage, cp.async double buffer.
// MODE 0: A=g_x, B=g_wt1, writes g_qkv fp16
// MODE 1: A=g_o, B=g_wt2, writes fp32 Cout (+bias)
// smem per buffer: A(10240) B(10240) = 20480; x2 = 40960
// ============================================================================
#define GEMM_SMEM 40960

template <int MODE>
__global__ __launch_bounds__(256, 2)
void gemm_tc(const float* __restrict__ bias, float* __restrict__ Cout)
{
    const __half* A  = (MODE == 0) ? g_x : g_o;
    const __half* Bw = (MODE == 0) ? g_wt1 : g_wt2;
    const int N = (MODE == 0) ? D3 : EMB;
    const int K = EMB;

    extern __shared__ char smem[];
    const uint32_t sb = smem_to_u32(smem);
    const int tid = threadIdx.x;
    const int wid = tid >> 5, lane = tid & 31;
    const int wm = wid & 3, wn = wid >> 2;
    const int m0 = blockIdx.y * 128, n0 = blockIdx.x * 128;

    // 4 x 16B cp.async chunks per thread per stage (2 streams x 512 chunks)
    const __half* csrc[4];
    uint32_t cdst[4];
#pragma unroll
    for (int i = 0; i < 4; i++) {
        int g = i * 256 + tid;
        int sub = g >> 9, c = g & 511, row = c >> 2, ch = c & 3;
        const __half* bp = (sub == 0) ? A + (long)m0 * K : Bw + (long)n0 * K;
        csrc[i] = bp + (long)row * K + ch * 8;
        cdst[i] = sb + sub * 10240 + row * 80 + ch * 16;
    }

#pragma unroll
    for (int i = 0; i < 4; i++) { CP_ASYNC16(cdst[i], csrc[i]); csrc[i] += 32; }
    CP_COMMIT();

    const uint32_t a_base = sb + (wm * 32 + (lane & 15)) * 80 + (lane >> 4) * 16;
    const uint32_t b_base = sb + 10240 +
        (wn * 64 + (lane & 7) + ((lane >> 4) & 1) * 8) * 80 + ((lane >> 3) & 1) * 16;

    float acc[2][8][4];
#pragma unroll
    for (int mf = 0; mf < 2; mf++)
#pragma unroll
        for (int nf = 0; nf < 8; nf++)
#pragma unroll
            for (int q = 0; q < 4; q++) acc[mf][nf][q] = 0.f;

    for (int ck = 0; ck < NCK; ck++) {
        const int buf = ck & 1;
        CP_WAIT0();
        __syncthreads();
        if (ck + 1 < NCK) {
            const uint32_t bo = (buf ^ 1) * 20480;
#pragma unroll
            for (int i = 0; i < 4; i++) { CP_ASYNC16(cdst[i] + bo, csrc[i]); csrc[i] += 32; }
            CP_COMMIT();
        }

        const uint32_t bofs = buf * 20480;
#pragma unroll
        for (int kk = 0; kk < 2; kk++) {
            const uint32_t ko = bofs + kk * 32;
            uint32_t a4[2][4];
#pragma unroll
            for (int mf = 0; mf < 2; mf++) {
                const uint32_t ao = a_base + mf * 1280 + ko;
                LDSM_X4(a4[mf][0], a4[mf][1], a4[mf][2], a4[mf][3], ao);
            }
#pragma unroll
            for (int nf = 0; nf < 4; nf++) {
                uint32_t b4[4];
                LDSM_X4(b4[0], b4[1], b4[2], b4[3], b_base + nf * 1280 + ko);
                MMA_F16(acc[0][nf * 2 + 0], a4[0], b4[0], b4[1]);
                MMA_F16(acc[1][nf * 2 + 0], a4[1], b4[0], b4[1]);
                MMA_F16(acc[0][nf * 2 + 1], a4[0], b4[2], b4[3]);
                MMA_F16(acc[1][nf * 2 + 1], a4[1], b4[2], b4[3]);
            }
        }
    }

    const int gid = lane >> 2, tig = lane & 3;
#pragma unroll
    for (int mf = 0; mf < 2; mf++) {
#pragma unroll
        for (int nf = 0; nf < 8; nf++) {
            const int col = n0 + wn * 64 + nf * 8 + tig * 2;
            const float bx0 = bias[col], bx1 = bias[col + 1];
            const int r0 = m0 + wm * 32 + mf * 16 + gid;
            float v00 = acc[mf][nf][0] + bx0, v01 = acc[mf][nf][1] + bx1;
            float v10 = acc[mf][nf][2] + bx0, v11 = acc[mf][nf][3] + bx1;
            if (MODE == 1) {
                float2 a0 = {v00, v01}, a1 = {v10, v11};
                *(float2*)&Cout[(long)r0 * N + col] = a0;
                *(float2*)&Cout[(long)(r0 + 8) * N + col] = a1;
            } else {
                *(uint32_t*)&g_qkv[(long)r0 * N + col] = pack_f16x2(v00, v01);
                *(uint32_t*)&g_qkv[(long)(r0 + 8) * N + col] = pack_f16x2(v10, v11);
            }
        }
    }
}

// ============================================================================
// HMMA flash attention, causal, single fp16 operands, fp32 softmax state.
// Q tile 128 x K tile 64, hs=64, 256 threads (8 warps x 16 q-rows).
// Pipelined K/V double-buffer stages (cp.async groups).
// ============================================================================
#define APITCH 144
#define SQ_BYTES  (128 * APITCH)          // 18432 (Q)
#define SKV_BYTES (64 * APITCH)           // 9216  (one K or V buffer)
#define ATTN_SMEM (SQ_BYTES + 2*SKV_BYTES + 2*SKV_BYTES)   // 55296

__global__ __launch_bounds__(256, 2)
void attn_tc()
{
    extern __shared__ char smem[];
    const uint32_t sb = smem_to_u32(smem);
    const uint32_t sQ = sb;                          // Q
    const uint32_t sK0 = sb + SQ_BYTES;              // K bufs: +buf*9216
    const uint32_t sV0 = sK0 + 2 * SKV_BYTES;        // V bufs: +buf*9216

    const int qt = gridDim.x - 1 - blockIdx.x;   // long blocks first
    const int h  = blockIdx.y;
    const int b  = blockIdx.z;
    const int tid = threadIdx.x;
    const int wid = tid >> 5, lane = tid & 31;
    const int gid = lane >> 2, tig = lane & 3;
    const int q0 = qt * 128;
    const long rowbase = (long)b * SEQ;
    const int nk = 2 * qt + 2;

    // ---- Q tile load (group 1): 128 rows x 8 chunks ----
#pragma unroll
    for (int it = 0; it < 4; it++) {
        int g = it * 256 + tid;
        int row = g >> 3, ch = g & 7;
        const __half* src = g_qkv + (rowbase + q0 + row) * D3 + h * HSZ + ch * 8;
        CP_ASYNC16(sQ + row * APITCH + ch * 16, src);
    }
    CP_COMMIT();

    // ---- K stage 0 load (group 2) ----
#pragma unroll
    for (int it = 0; it < 2; it++) {
        int g = it * 256 + tid;
        int row = g >> 3, ch = g & 7;
        const __half* src = g_qkv + (rowbase + row) * D3 + EMB + h * HSZ + ch * 8;
        CP_ASYNC16(sK0 + row * APITCH + ch * 16, src);
    }
    CP_COMMIT();

    const uint32_t a_base = sQ + (wid * 16 + (lane & 15)) * APITCH + (lane >> 4) * 16;
    const uint32_t bk_off = ((lane & 7) + ((lane >> 4) & 1) * 8) * APITCH
                              + ((lane >> 3) & 1) * 16;
    const uint32_t v_off = ((lane & 7) + ((lane >> 3) & 1) * 8) * APITCH
                              + (lane >> 4) * 16;

    float oacc[8][4];
#pragma unroll
    for (int df = 0; df < 8; df++)
#pragma unroll
        for (int q = 0; q < 4; q++) oacc[df][q] = 0.f;
    float mrow[2] = {-1e30f, -1e30f};
    float lrow[2] = {0.f, 0.f};

    const int qr0 = q0 + wid * 16 + gid;
    const int qr1 = qr0 + 8;

    for (int kt = 0; kt < nk; kt++) {
        const int k0 = kt * 64;
        const int buf = kt & 1;

        // ---- issue V_kt ----
#pragma unroll
        for (int it = 0; it < 2; it++) {
            int g = it * 256 + tid;
            int row = g >> 3, ch = g & 7;
            const __half* src = g_qkv + (rowbase + k0 + row) * D3
                                + 2 * EMB + h * HSZ + ch * 8;
            CP_ASYNC16(sV0 + buf * SKV_BYTES + row * APITCH + ch * 16, src);
        }
        CP_COMMIT();
        // ---- issue K_{kt+1} (clamped re-load on last stage) ----
        {
            const int kn0 = (kt + 1 < nk) ? (kt + 1) * 64 : 0;
#pragma unroll
            for (int it = 0; it < 2; it++) {
                int g = it * 256 + tid;
                int row = g >> 3, ch = g & 7;
                const __half* src = g_qkv + (rowbase + kn0 + row) * D3
                                    + EMB + h * HSZ + ch * 8;
                CP_ASYNC16(sK0 + (buf ^ 1) * SKV_BYTES + row * APITCH + ch * 16, src);
            }
            CP_COMMIT();
        }

        CP_WAIT2();            // K_kt (and Q on kt=0) landed
        __syncthreads();

        // ---- QK^T scores ----
        const uint32_t bk_base = sK0 + buf * SKV_BYTES + bk_off;
        float sacc[8][4];
#pragma unroll
        for (int nf = 0; nf < 8; nf++)
#pragma unroll
            for (int q = 0; q < 4; q++) sacc[nf][q] = 0.f;

#pragma unroll
        for (int ks = 0; ks < 4; ks++) {
            uint32_t q4[4];
            LDSM_X4(q4[0], q4[1], q4[2], q4[3], a_base + ks * 32);
#pragma unroll
            for (int nb = 0; nb < 4; nb++) {
                uint32_t k4[4];
                LDSM_X4(k4[0], k4[1], k4[2], k4[3],
                        bk_base + nb * (16 * APITCH) + ks * 32);
                MMA_F16(sacc[nb * 2 + 0], q4, k4[0], k4[1]);
                MMA_F16(sacc[nb * 2 + 1], q4, k4[2], k4[3]);
            }
        }

        CP_WAIT1();            // V_kt landed (K_{kt+1} still in flight)
        __syncthreads();

        // ---- scale + causal mask + row max ----
        const bool maskst = (kt >= 2 * qt);
        float tm0 = -1e30f, tm1 = -1e30f;
#pragma unroll
        for (int nf = 0; nf < 8; nf++) {
            const int c = k0 + nf * 8 + 2 * tig;
            float v0 = sacc[nf][0] * 0.125f;
            float v1 = sacc[nf][1] * 0.125f;
            float v2 = sacc[nf][2] * 0.125f;
            float v3 = sacc[nf][3] * 0.125f;
            if (maskst) {
                if (c     > qr0) v0 = -1e30f;
                if (c + 1 > qr0) v1 = -1e30f;
                if (c     > qr1) v2 = -1e30f;
                if (c + 1 > qr1) v3 = -1e30f;
            }
            sacc[nf][0] = v0; sacc[nf][1] = v1;
            sacc[nf][2] = v2; sacc[nf][3] = v3;
            tm0 = fmaxf(tm0, fmaxf(v0, v1));
            tm1 = fmaxf(tm1, fmaxf(v2, v3));
        }
        tm0 = fmaxf(tm0, __shfl_xor_sync(0xffffffffu, tm0, 1));
        tm0 = fmaxf(tm0, __shfl_xor_sync(0xffffffffu, tm0, 2));
        tm1 = fmaxf(tm1, __shfl_xor_sync(0xffffffffu, tm1, 1));
        tm1 = fmaxf(tm1, __shfl_xor_sync(0xffffffffu, tm1, 2));

        const float mn0 = fmaxf(mrow[0], tm0);
        const float mn1 = fmaxf(mrow[1], tm1);
        const float esc0 = __expf(mrow[0] - mn0);
        const float esc1 = __expf(mrow[1] - mn1);
        mrow[0] = mn0; mrow[1] = mn1;
#pragma unroll
        for (int df = 0; df < 8; df++) {
            oacc[df][0] *= esc0; oacc[df][1] *= esc0;
            oacc[df][2] *= esc1; oacc[df][3] *= esc1;
        }

        // ---- exp + row sums ----
        float ps0 = 0.f, ps1 = 0.f;
#pragma unroll
        for (int nf = 0; nf < 8; nf++) {
            float p0 = __expf(sacc[nf][0] - mn0);
            float p1 = __expf(sacc[nf][1] - mn0);
            float p2 = __expf(sacc[nf][2] - mn1);
            float p3 = __expf(sacc[nf][3] - mn1);
            ps0 += p0 + p1; ps1 += p2 + p3;
            sacc[nf][0] = p0; sacc[nf][1] = p1;
            sacc[nf][2] = p2; sacc[nf][3] = p3;
        }
        ps0 += __shfl_xor_sync(0xffffffffu, ps0, 1);
        ps0 += __shfl_xor_sync(0xffffffffu, ps0, 2);
        ps1 += __shfl_xor_sync(0xffffffffu, ps1, 1);
        ps1 += __shfl_xor_sync(0xffffffffu, ps1, 2);
        lrow[0] = lrow[0] * esc0 + ps0;
        lrow[1] = lrow[1] * esc1 + ps1;

        // ---- PV: repack P C-frags -> A-frags (fp16), MMA with V (trans) ----
        const uint32_t v_base = sV0 + buf * SKV_BYTES + v_off;
#pragma unroll
        for (int ks = 0; ks < 4; ks++) {
            const int f0 = 2 * ks, f1 = 2 * ks + 1;
            uint32_t pa[4];
            pa[0] = pack_f16x2(sacc[f0][0], sacc[f0][1]);
            pa[1] = pack_f16x2(sacc[f0][2], sacc[f0][3]);
            pa[2] = pack_f16x2(sacc[f1][0], sacc[f1][1]);
            pa[3] = pack_f16x2(sacc[f1][2], sacc[f1][3]);
#pragma unroll
            for (int nb = 0; nb < 4; nb++) {
                uint32_t v4[4];
                LDSM_X4T(v4[0], v4[1], v4[2], v4[3],
                         v_base + ks * (16 * APITCH) + nb * 32);
                MMA_F16(oacc[nb * 2 + 0], pa, v4[0], v4[1]);
                MMA_F16(oacc[nb * 2 + 1], pa, v4[2], v4[3]);
            }
        }
    }

    // ---- finalize: O = oacc/l, fp16, write g_o ----
    const float inv0 = 1.f / lrow[0];
    const float inv1 = 1.f / lrow[1];
#pragma unroll
    for (int df = 0; df < 8; df++) {
        const int col = h * HSZ + df * 8 + 2 * tig;
        *(uint32_t*)&g_o[(rowbase + qr0) * EMB + col] =
            pack_f16x2(oacc[df][0] * inv0, oacc[df][1] * inv0);
        *(uint32_t*)&g_o[(rowbase + qr1) * EMB + col] =
            pack_f16x2(oacc[df][2] * inv1, oacc[df][3] * inv1);
    }
}

// ---------------------------------------------------------------------------
extern "C" void kernel_launch(void* const* d_in, const int* in_sizes, int n_in,
                              void* d_out, int out_size)
{
    const float* x     = (const float*)d_in[0];
    const float* W_qkv = (const float*)d_in[1];
    const float* b_qkv = (const float*)d_in[2];
    const float* W_out = (const float*)d_in[3];
    const float* b_out = (const float*)d_in[4];
    float* out = (float*)d_out;

    // 0) weight transpose (fp16); x fp16 convert
    prep_wt<0><<<dim3(D3 / 32, EMB / 32), dim3(32, 8)>>>(W_qkv, EMB, D3);
    prep_wt<1><<<dim3(EMB / 32, EMB / 32), dim3(32, 8)>>>(W_out, EMB, EMB);
    prep_x<<<ROWS * EMB / 4 / 256, 256>>>(x);

    // 1) QKV projection (HMMA fp16)
    cudaFuncSetAttribute(gemm_tc<0>, cudaFuncAttributeMaxDynamicSharedMemorySize, GEMM_SMEM);
    gemm_tc<0><<<dim3(D3 / 128, ROWS / 128), 256, GEMM_SMEM>>>(b_qkv, nullptr);

    // 2) causal flash attention (HMMA fp16)
    cudaFuncSetAttribute(attn_tc, cudaFuncAttributeMaxDynamicSharedMemorySize, ATTN_SMEM);
    attn_tc<<<dim3(SEQ / 128, NH, BATCH), 256, ATTN_SMEM>>>();

    // 3) output projection (HMMA fp16), fp32 out + bias
    cudaFuncSetAttribute(gemm_tc<1>, cudaFuncAttributeMaxDynamicSharedMemorySize, GEMM_SMEM);
    gemm_tc<1><<<dim3(EMB / 128, ROWS / 128), 256, GEMM_SMEM>>>(b_out, out);
}

// round 12
// speedup vs baseline: 2.2914x; 1.0047x over previous
#include <cuda_runtime.h>
#include <cuda_fp16.h>
#include <cstdint>

#define SEQ   2048
#define EMB   1024
#define NH    16
#define HSZ   64
#define BATCH 2
#define ROWS  (BATCH * SEQ)     // 4096
#define D3    (3 * EMB)         // 3072
#define NCK   (EMB / 32)        // 32 k-stages of BK=32 for projection GEMMs

// Scratch (device globals — no allocation allowed)
__device__ __half g_qkv[ROWS * D3];    // qkv fp16 [b*s][3*EMB]
__device__ __half g_wt1[D3 * EMB];     // W_qkv^T fp16 [3072,1024] (K-major)
__device__ __half g_wt2[EMB * EMB];    // W_out^T fp16
__device__ __half g_x[ROWS * EMB];     // x fp16
__device__ __half g_o[ROWS * EMB];     // attn-out fp16

// ============================================================================
// asm helpers (plain sm_80+ PTX — legal on target sm_103)
// ============================================================================
__device__ __forceinline__ uint32_t smem_to_u32(const void* p) {
    uint32_t a;
    asm("{ .reg .u64 t; cvta.to.shared.u64 t, %1; cvt.u32.u64 %0, t; }"
        : "=r"(a) : "l"(p));
    return a;
}

#define CP_ASYNC16(dst, src) \
    asm volatile("cp.async.cg.shared.global [%0], [%1], 16;" \
                 :: "r"(dst), "l"(__cvta_generic_to_global(src)) : "memory")
#define CP_COMMIT() asm volatile("cp.async.commit_group;" ::: "memory")
#define CP_WAIT1()  asm volatile("cp.async.wait_group 1;" ::: "memory")
#define CP_WAIT2()  asm volatile("cp.async.wait_group 2;" ::: "memory")

#define LDSM_X4(r0, r1, r2, r3, addr) \
    asm volatile("ldmatrix.sync.aligned.m8n8.x4.shared.b16 {%0,%1,%2,%3}, [%4];" \
                 : "=r"(r0), "=r"(r1), "=r"(r2), "=r"(r3) : "r"(addr))
#define LDSM_X4T(r0, r1, r2, r3, addr) \
    asm volatile("ldmatrix.sync.aligned.m8n8.x4.trans.shared.b16 {%0,%1,%2,%3}, [%4];" \
                 : "=r"(r0), "=r"(r1), "=r"(r2), "=r"(r3) : "r"(addr))

#define MMA_F16(d, a, b0v, b1v) \
    asm volatile("mma.sync.aligned.m16n8k16.row.col.f32.f16.f16.f32 " \
                 "{%0,%1,%2,%3}, {%4,%5,%6,%7}, {%8,%9}, {%0,%1,%2,%3};" \
                 : "+f"((d)[0]), "+f"((d)[1]), "+f"((d)[2]), "+f"((d)[3]) \
                 : "r"((a)[0]), "r"((a)[1]), "r"((a)[2]), "r"((a)[3]), \
                   "r"(b0v), "r"(b1v))

// pack two f32 -> f16x2 (first arg in low half)
__device__ __forceinline__ uint32_t pack_f16x2(float lo, float hi) {
    uint32_t r;
    asm("cvt.rn.f16x2.f32 %0, %1, %2;" : "=r"(r) : "f"(hi), "f"(lo));
    return r;
}

// ============================================================================
// Unified prep (one launch): W_qkv^T, W_out^T (fp16), x (fp16).
// grid = 3072 (wt1 tiles) + 1024 (wt2 tiles) + 4096 (x blocks) = 8192 x 256thr
// ============================================================================
__global__ void prep_all(const float* __restrict__ x,
                         const float* __restrict__ W_qkv,
                         const float* __restrict__ W_out)
{
    const int bid = blockIdx.x;
    const int tid = threadIdx.x;
    if (bid < 4096) {
        // weight transpose tile (32x32)
        __shared__ float t[32][33];
        const float* W; __half* Wt; int K, N, n0, k0;
        if (bid < 3072) {
            W = W_qkv; Wt = g_wt1; K = EMB; N = D3;
            n0 = (bid % 96) * 32; k0 = (bid / 96) * 32;
        } else {
            const int b2 = bid - 3072;
            W = W_out; Wt = g_wt2; K = EMB; N = EMB;
            n0 = (b2 % 32) * 32; k0 = (b2 / 32) * 32;
        }
        const int tx = tid & 31, ty = tid >> 5;   // 32 x 8
#pragma unroll
        for (int j = 0; j < 32; j += 8)
            t[ty + j][tx] = W[(long)(k0 + ty + j) * N + n0 + tx];
        __syncthreads();
#pragma unroll
        for (int j = 0; j < 32; j += 8) {
            const int n = n0 + ty + j, k = k0 + tx;
            Wt[(long)n * K + k] = __float2half_rn(t[tx][ty + j]);
        }
    } else {
        // x fp32 -> fp16 (float4 granularity)
        const long i = (long)(bid - 4096) * 256 + tid;
        float4 v = ((const float4*)x)[i];
        uint2 u;
        u.x = pack_f16x2(v.x, v.y);
        u.y = pack_f16x2(v.z, v.w);
        ((uint2*)g_x)[i] = u;
    }
}

// ============================================================================
// HMMA GEMM + bias, single fp16. CTA 128x128, BK=32, 8 warps (4m x 2n).
// 4-stage cp.async pipeline, one __syncthreads per k-stage:
//   [WAIT2 (stage ck ready); sync; issue ck+3; compute ck]
// MODE 0: A=g_x, B=g_wt1, writes g_qkv fp16
// MODE 1: A=g_o, B=g_wt2, writes fp32 Cout (+bias)
// smem: 4 stages x (A 10240 + B 10240) = 81920
// ============================================================================
#define STG 20480
#define GEMM_SMEM (4 * STG)

template <int MODE>
__global__ __launch_bounds__(256, 2)
void gemm_tc(const float* __restrict__ bias, float* __restrict__ Cout)
{
    const __half* A  = (MODE == 0) ? g_x : g_o;
    const __half* Bw = (MODE == 0) ? g_wt1 : g_wt2;
    const int N = (MODE == 0) ? D3 : EMB;
    const int K = EMB;

    extern __shared__ char smem[];
    const uint32_t sb = smem_to_u32(smem);
    const int tid = threadIdx.x;
    const int wid = tid >> 5, lane = tid & 31;
    const int wm = wid & 3, wn = wid >> 2;
    const int m0 = blockIdx.y * 128, n0 = blockIdx.x * 128;

    // 4 x 16B cp.async chunks per thread per stage (2 streams x 512 chunks)
    const __half* csrc[4];
    uint32_t cdst[4];
#pragma unroll
    for (int i = 0; i < 4; i++) {
        int g = i * 256 + tid;
        int sub = g >> 9, c = g & 511, row = c >> 2, ch = c & 3;
        const __half* bp = (sub == 0) ? A + (long)m0 * K : Bw + (long)n0 * K;
        csrc[i] = bp + (long)row * K + ch * 8;
        cdst[i] = sb + sub * 10240 + row * 80 + ch * 16;
    }

    // prologue: stages 0,1,2
#pragma unroll
    for (int s = 0; s < 3; s++) {
#pragma unroll
        for (int i = 0; i < 4; i++) {
            CP_ASYNC16(cdst[i] + s * STG, csrc[i]);
            csrc[i] += 32;
        }
        CP_COMMIT();
    }

    const uint32_t a_base = sb + (wm * 32 + (lane & 15)) * 80 + (lane >> 4) * 16;
    const uint32_t b_base = sb + 10240 +
        (wn * 64 + (lane & 7) + ((lane >> 4) & 1) * 8) * 80 + ((lane >> 3) & 1) * 16;

    float acc[2][8][4];
#pragma unroll
    for (int mf = 0; mf < 2; mf++)
#pragma unroll
        for (int nf = 0; nf < 8; nf++)
#pragma unroll
            for (int q = 0; q < 4; q++) acc[mf][nf][q] = 0.f;

    for (int ck = 0; ck < NCK; ck++) {
        CP_WAIT2();            // stage ck landed (pending <= 2 newest)
        __syncthreads();       // visible to all; all warps done with buf (ck+3)&3

        // issue stage ck+3 (clamped dummy reload keeps group counts uniform)
        {
            const int s = ck + 3;
            const uint32_t bo = (uint32_t)(s & 3) * STG;
            const bool real = (s < NCK);
#pragma unroll
            for (int i = 0; i < 4; i++) {
                const __half* src = real ? csrc[i] : csrc[i] - 32;
                CP_ASYNC16(cdst[i] + bo, src);
                if (real) csrc[i] += 32;
            }
            CP_COMMIT();
        }

        const uint32_t bofs = (uint32_t)(ck & 3) * STG;
#pragma unroll
        for (int kk = 0; kk < 2; kk++) {
            const uint32_t ko = bofs + kk * 32;
            uint32_t a4[2][4];
#pragma unroll
            for (int mf = 0; mf < 2; mf++) {
                const uint32_t ao = a_base + mf * 1280 + ko;
                LDSM_X4(a4[mf][0], a4[mf][1], a4[mf][2], a4[mf][3], ao);
            }
#pragma unroll
            for (int nf = 0; nf < 4; nf++) {
                uint32_t b4[4];
                LDSM_X4(b4[0], b4[1], b4[2], b4[3], b_base + nf * 1280 + ko);
                MMA_F16(acc[0][nf * 2 + 0], a4[0], b4[0], b4[1]);
                MMA_F16(acc[1][nf * 2 + 0], a4[1], b4[0], b4[1]);
                MMA_F16(acc[0][nf * 2 + 1], a4[0], b4[2], b4[3]);
                MMA_F16(acc[1][nf * 2 + 1], a4[1], b4[2], b4[3]);
            }
        }
    }

    const int gid = lane >> 2, tig = lane & 3;
#pragma unroll
    for (int mf = 0; mf < 2; mf++) {
#pragma unroll
        for (int nf = 0; nf < 8; nf++) {
            const int col = n0 + wn * 64 + nf * 8 + tig * 2;
            const float bx0 = bias[col], bx1 = bias[col + 1];
            const int r0 = m0 + wm * 32 + mf * 16 + gid;
            float v00 = acc[mf][nf][0] + bx0, v01 = acc[mf][nf][1] + bx1;
            float v10 = acc[mf][nf][2] + bx0, v11 = acc[mf][nf][3] + bx1;
            if (MODE == 1) {
                float2 a0 = {v00, v01}, a1 = {v10, v11};
                *(float2*)&Cout[(long)r0 * N + col] = a0;
                *(float2*)&Cout[(long)(r0 + 8) * N + col] = a1;
            } else {
                *(uint32_t*)&g_qkv[(long)r0 * N + col] = pack_f16x2(v00, v01);
                *(uint32_t*)&g_qkv[(long)(r0 + 8) * N + col] = pack_f16x2(v10, v11);
            }
        }
    }
}

// ============================================================================
// HMMA flash attention, causal, single fp16 operands, fp32 softmax state.
// Q tile 128 x K tile 64, hs=64, 256 threads (8 warps x 16 q-rows).
// Triple-buffered K AND V issued 2 stages ahead; ONE __syncthreads per stage:
//   [WAIT1 (stage kt ready); sync; issue K/V_{kt+2}; compute kt]
// ============================================================================
#define APITCH 144
#define SQ_BYTES  (128 * APITCH)          // 18432 (Q)
#define SKV_BYTES (64 * APITCH)           // 9216  (one K or V buffer)
#define ATTN_SMEM (SQ_BYTES + 3*SKV_BYTES + 3*SKV_BYTES)   // 73728

__global__ __launch_bounds__(256, 2)
void attn_tc()
{
    extern __shared__ char smem[];
    const uint32_t sb = smem_to_u32(smem);
    const uint32_t sQ = sb;                          // Q
    const uint32_t sK0 = sb + SQ_BYTES;              // K bufs: + (s%3)*9216
    const uint32_t sV0 = sK0 + 3 * SKV_BYTES;        // V bufs: + (s%3)*9216

    const int qt = gridDim.x - 1 - blockIdx.x;   // long blocks first
    const int h  = blockIdx.y;
    const int b  = blockIdx.z;
    const int tid = threadIdx.x;
    const int wid = tid >> 5, lane = tid & 31;
    const int gid = lane >> 2, tig = lane & 3;
    const int q0 = qt * 128;
    const long rowbase = (long)b * SEQ;
    const int nk = 2 * qt + 2;

    // KV stage issue helper (clamped for dummy tail stages)
    auto issue_kv = [&](int s) {
        const int kr = (s < nk) ? s * 64 : 0;
        const uint32_t kb = sK0 + (uint32_t)(s % 3) * SKV_BYTES;
        const uint32_t vb = sV0 + (uint32_t)(s % 3) * SKV_BYTES;
#pragma unroll
        for (int it = 0; it < 2; it++) {
            int g = it * 256 + tid;
            int row = g >> 3, ch = g & 7;
            const __half* base = g_qkv + (rowbase + kr + row) * D3 + h * HSZ + ch * 8;
            CP_ASYNC16(kb + row * APITCH + ch * 16, base + EMB);
            CP_ASYNC16(vb + row * APITCH + ch * 16, base + 2 * EMB);
        }
    };

    // ---- prologue: group0 = Q + K0 + V0; group1 = K1 + V1 ----
#pragma unroll
    for (int it = 0; it < 4; it++) {
        int g = it * 256 + tid;
        int row = g >> 3, ch = g & 7;
        const __half* src = g_qkv + (rowbase + q0 + row) * D3 + h * HSZ + ch * 8;
        CP_ASYNC16(sQ + row * APITCH + ch * 16, src);
    }
    issue_kv(0);
    CP_COMMIT();
    issue_kv(1);
    CP_COMMIT();

    const uint32_t a_base = sQ + (wid * 16 + (lane & 15)) * APITCH + (lane >> 4) * 16;
    const uint32_t bk_off = ((lane & 7) + ((lane >> 4) & 1) * 8) * APITCH
                              + ((lane >> 3) & 1) * 16;
    const uint32_t v_off = ((lane & 7) + ((lane >> 3) & 1) * 8) * APITCH
                              + (lane >> 4) * 16;

    float oacc[8][4];
#pragma unroll
    for (int df = 0; df < 8; df++)
#pragma unroll
        for (int q = 0; q < 4; q++) oacc[df][q] = 0.f;
    float mrow[2] = {-1e30f, -1e30f};
    float lrow[2] = {0.f, 0.f};

    const int qr0 = q0 + wid * 16 + gid;
    const int qr1 = qr0 + 8;

    for (int kt = 0; kt < nk; kt++) {
        const int k0 = kt * 64;
        const uint32_t bufo = (uint32_t)(kt % 3) * SKV_BYTES;

        CP_WAIT1();            // stage kt (and Q on kt=0) landed
        __syncthreads();       // data visible; all warps done with buf (kt+2)%3
        issue_kv(kt + 2);      // prefetch 2 stages ahead
        CP_COMMIT();

        // ---- QK^T scores ----
        const uint32_t bk_base = sK0 + bufo + bk_off;
        float sacc[8][4];
#pragma unroll
        for (int nf = 0; nf < 8; nf++)
#pragma unroll
            for (int q = 0; q < 4; q++) sacc[nf][q] = 0.f;

#pragma unroll
        for (int ks = 0; ks < 4; ks++) {
            uint32_t q4[4];
            LDSM_X4(q4[0], q4[1], q4[2], q4[3], a_base + ks * 32);
#pragma unroll
            for (int nb = 0; nb < 4; nb++) {
                uint32_t k4[4];
                LDSM_X4(k4[0], k4[1], k4[2], k4[3],
                        bk_base + nb * (16 * APITCH) + ks * 32);
                MMA_F16(sacc[nb * 2 + 0], q4, k4[0], k4[1]);
                MMA_F16(sacc[nb * 2 + 1], q4, k4[2], k4[3]);
            }
        }

        // ---- scale + causal mask + row max ----
        const bool maskst = (kt >= 2 * qt);
        float tm0 = -1e30f, tm1 = -1e30f;
#pragma unroll
        for (int nf = 0; nf < 8; nf++) {
            const int c = k0 + nf * 8 + 2 * tig;
            float v0 = sacc[nf][0] * 0.125f;
            float v1 = sacc[nf][1] * 0.125f;
            float v2 = sacc[nf][2] * 0.125f;
            float v3 = sacc[nf][3] * 0.125f;
            if (maskst) {
                if (c     > qr0) v0 = -1e30f;
                if (c + 1 > qr0) v1 = -1e30f;
                if (c     > qr1) v2 = -1e30f;
                if (c + 1 > qr1) v3 = -1e30f;
            }
            sacc[nf][0] = v0; sacc[nf][1] = v1;
            sacc[nf][2] = v2; sacc[nf][3] = v3;
            tm0 = fmaxf(tm0, fmaxf(v0, v1));
            tm1 = fmaxf(tm1, fmaxf(v2, v3));
        }
        tm0 = fmaxf(tm0, __shfl_xor_sync(0xffffffffu, tm0, 1));
        tm0 = fmaxf(tm0, __shfl_xor_sync(0xffffffffu, tm0, 2));
        tm1 = fmaxf(tm1, __shfl_xor_sync(0xffffffffu, tm1, 1));
        tm1 = fmaxf(tm1, __shfl_xor_sync(0xffffffffu, tm1, 2));

        const float mn0 = fmaxf(mrow[0], tm0);
        const float mn1 = fmaxf(mrow[1], tm1);
        const float esc0 = __expf(mrow[0] - mn0);
        const float esc1 = __expf(mrow[1] - mn1);
        mrow[0] = mn0; mrow[1] = mn1;
#pragma unroll
        for (int df = 0; df < 8; df++) {
            oacc[df][0] *= esc0; oacc[df][1] *= esc0;
            oacc[df][2] *= esc1; oacc[df][3] *= esc1;
        }

        // ---- exp + row sums ----
        float ps0 = 0.f, ps1 = 0.f;
#pragma unroll
        for (int nf = 0; nf < 8; nf++) {
            float p0 = __expf(sacc[nf][0] - mn0);
            float p1 = __expf(sacc[nf][1] - mn0);
            float p2 = __expf(sacc[nf][2] - mn1);
            float p3 = __expf(sacc[nf][3] - mn1);
            ps0 += p0 + p1; ps1 += p2 + p3;
            sacc[nf][0] = p0; sacc[nf][1] = p1;
            sacc[nf][2] = p2; sacc[nf][3] = p3;
        }
        ps0 += __shfl_xor_sync(0xffffffffu, ps0, 1);
        ps0 += __shfl_xor_sync(0xffffffffu, ps0, 2);
        ps1 += __shfl_xor_sync(0xffffffffu, ps1, 1);
        ps1 += __shfl_xor_sync(0xffffffffu, ps1, 2);
        lrow[0] = lrow[0] * esc0 + ps0;
        lrow[1] = lrow[1] * esc1 + ps1;

        // ---- PV: repack P C-frags -> A-frags (fp16), MMA with V (trans) ----
        const uint32_t v_base = sV0 + bufo + v_off;
#pragma unroll
        for (int ks = 0; ks < 4; ks++) {
            const int f0 = 2 * ks, f1 = 2 * ks + 1;
            uint32_t pa[4];
            pa[0] = pack_f16x2(sacc[f0][0], sacc[f0][1]);
            pa[1] = pack_f16x2(sacc[f0][2], sacc[f0][3]);
            pa[2] = pack_f16x2(sacc[f1][0], sacc[f1][1]);
            pa[3] = pack_f16x2(sacc[f1][2], sacc[f1][3]);
#pragma unroll
            for (int nb = 0; nb < 4; nb++) {
                uint32_t v4[4];
                LDSM_X4T(v4[0], v4[1], v4[2], v4[3],
                         v_base + ks * (16 * APITCH) + nb * 32);
                MMA_F16(oacc[nb * 2 + 0], pa, v4[0], v4[1]);
                MMA_F16(oacc[nb * 2 + 1], pa, v4[2], v4[3]);
            }
        }
    }

    // ---- finalize: O = oacc/l, fp16, write g_o ----
    const float inv0 = 1.f / lrow[0];
    const float inv1 = 1.f / lrow[1];
#pragma unroll
    for (int df = 0; df < 8; df++) {
        const int col = h * HSZ + df * 8 + 2 * tig;
        *(uint32_t*)&g_o[(rowbase + qr0) * EMB + col] =
            pack_f16x2(oacc[df][0] * inv0, oacc[df][1] * inv0);
        *(uint32_t*)&g_o[(rowbase + qr1) * EMB + col] =
            pack_f16x2(oacc[df][2] * inv1, oacc[df][3] * inv1);
    }
}

// ---------------------------------------------------------------------------
extern "C" void kernel_launch(void* const* d_in, const int* in_sizes, int n_in,
                              void* d_out, int out_size)
{
    const float* x     = (const float*)d_in[0];
    const float* W_qkv = (const float*)d_in[1];
    const float* b_qkv = (const float*)d_in[2];
    const float* W_out = (const float*)d_in[3];
    const float* b_out = (const float*)d_in[4];
    float* out = (float*)d_out;

    // 0) unified prep: W transposes (fp16) + x convert — one launch
    prep_all<<<8192, 256>>>(x, W_qkv, W_out);

    // 1) QKV projection (HMMA fp16, 4-stage pipeline)
    cudaFuncSetAttribute(gemm_tc<0>, cudaFuncAttributeMaxDynamicSharedMemorySize, GEMM_SMEM);
    gemm_tc<0><<<dim3(D3 / 128, ROWS / 128), 256, GEMM_SMEM>>>(b_qkv, nullptr);

    // 2) causal flash attention (HMMA fp16, 2-ahead K/V prefetch)
    cudaFuncSetAttribute(attn_tc, cudaFuncAttributeMaxDynamicSharedMemorySize, ATTN_SMEM);
    attn_tc<<<dim3(SEQ / 128, NH, BATCH), 256, ATTN_SMEM>>>();

    // 3) output projection (HMMA fp16), fp32 out + bias
    cudaFuncSetAttribute(gemm_tc<1>, cudaFuncAttributeMaxDynamicSharedMemorySize, GEMM_SMEM);
    gemm_tc<1><<<dim3(EMB / 128, ROWS / 128), 256, GEMM_SMEM>>>(b_out, out);
}